// round 2
// baseline (speedup 1.0000x reference)
#include <cuda_runtime.h>
#include <math.h>

// ---------------- problem constants ----------------
#define T_TOK   16384          // 4*64*64 tokens
#define DIM     768
#define FF      2048
#define NE      8
#define SLOTS   (2*T_TOK)      // 32768 (token, slot) rows
#define BM      128
#define BN      128
#define BK      8
#define ROWS_PAD_MAX (SLOTS + NE*BM)   // 33792 (each expert segment padded to BM)
#define ROW_TILES    (ROWS_PAD_MAX/BM) // 264

// ---------------- device scratch (no allocs allowed) ----------------
__device__ float g_H [(size_t)ROWS_PAD_MAX * FF];   // fc1 output (post-gelu)   ~277MB
__device__ float g_Y [(size_t)ROWS_PAD_MAX * DIM];  // fc2 output (per slot)    ~104MB
__device__ float g_G [(size_t)T_TOK * FF];          // shared h1 / gated prod   ~134MB
__device__ float g_G3[(size_t)T_TOK * FF];          // shared h3                ~134MB
__device__ int   g_rowtoken[ROWS_PAD_MAX];
__device__ int   g_rowmap[SLOTS];
__device__ float g_slotw[SLOTS];
__device__ int   g_slote[SLOTS];
__device__ int   g_counts[NE];
__device__ int   g_cursor[NE];
__device__ int   g_base[NE+1];

__device__ __forceinline__ float gelu_exact(float v) {
    return 0.5f * v * (1.0f + erff(v * 0.7071067811865475f));
}

// ---------------- init ----------------
__global__ void init_kernel() {
    int i = blockIdx.x * blockDim.x + threadIdx.x;
    if (i < ROWS_PAD_MAX) g_rowtoken[i] = -1;
    if (i < NE) { g_counts[i] = 0; g_cursor[i] = 0; }
}

// ---------------- gate: softmax + top2 + renorm ----------------
__global__ __launch_bounds__(256) void gate_kernel(const float* __restrict__ x,
                                                   const float* __restrict__ gw) {
    __shared__ float sgw[NE * DIM];
    for (int i = threadIdx.x; i < NE * DIM; i += 256) sgw[i] = gw[i];
    __syncthreads();
    int warp = threadIdx.x >> 5, lane = threadIdx.x & 31;
    int t = blockIdx.x * 8 + warp;
    if (t >= T_TOK) return;
    const float* xr = x + (size_t)t * DIM;
    float xv[24];
#pragma unroll
    for (int j = 0; j < 24; j++) xv[j] = xr[lane + 32 * j];
    float logit[NE];
#pragma unroll
    for (int e = 0; e < NE; e++) {
        float p = 0.f;
#pragma unroll
        for (int j = 0; j < 24; j++) p += xv[j] * sgw[e * DIM + lane + 32 * j];
#pragma unroll
        for (int off = 16; off > 0; off >>= 1) p += __shfl_down_sync(0xffffffffu, p, off);
        logit[e] = p;
    }
    if (lane == 0) {
        float m = logit[0];
#pragma unroll
        for (int e = 1; e < NE; e++) m = fmaxf(m, logit[e]);
        int a = 0;
#pragma unroll
        for (int e = 1; e < NE; e++) if (logit[e] > logit[a]) a = e;
        int b = (a == 0) ? 1 : 0;
#pragma unroll
        for (int e = 0; e < NE; e++) { if (e == a || e == b) continue; if (logit[e] > logit[b]) b = e; }
        float pa = expf(logit[a] - m), pb = expf(logit[b] - m);
        float inv = 1.f / (pa + pb);
        g_slote[2 * t] = a;  g_slote[2 * t + 1] = b;
        g_slotw[2 * t] = pa * inv;  g_slotw[2 * t + 1] = pb * inv;
        atomicAdd(&g_counts[a], 1);
        atomicAdd(&g_counts[b], 1);
    }
}

// ---------------- scan: padded expert bases ----------------
__global__ void scan_kernel() {
    if (threadIdx.x == 0 && blockIdx.x == 0) {
        int b = 0; g_base[0] = 0;
        for (int e = 0; e < NE; e++) {
            b += ((g_counts[e] + BM - 1) / BM) * BM;
            g_base[e + 1] = b;
        }
    }
}

// ---------------- assign rows ----------------
__global__ void assign_kernel() {
    int t = blockIdx.x * blockDim.x + threadIdx.x;
    if (t >= T_TOK) return;
#pragma unroll
    for (int k = 0; k < 2; k++) {
        int e = g_slote[2 * t + k];
        int pos = atomicAdd(&g_cursor[e], 1);
        int row = g_base[e] + pos;
        g_rowmap[2 * t + k] = row;
        g_rowtoken[row] = t;
    }
}

// ---------------- routed fc1 (gathered) + gelu ----------------
__global__ __launch_bounds__(256, 2) void fc1_kernel(const float* __restrict__ x,
                                                     const float* __restrict__ w,
                                                     const float* __restrict__ bias) {
    int rstart = blockIdx.x * BM;
    if (rstart >= g_base[NE]) return;
    int e = 0;
#pragma unroll
    for (int i = 0; i < NE; i++) if (rstart >= g_base[i + 1]) e = i + 1;
    const float* We = w + (size_t)e * FF * DIM;
    int n0 = blockIdx.y * BN;
    __shared__ float As[BK][BM];
    __shared__ float Bs[BK][BN];
    int tid = threadIdx.x;
    int lm = tid & 127, lk = tid >> 7;
    int tok = g_rowtoken[rstart + lm];
    const float* arow = (tok >= 0) ? x + (size_t)tok * DIM : 0;
    const float* brow = We + (size_t)(n0 + lm) * DIM;
    int tx = tid & 15, ty = tid >> 4;
    float acc[8][8];
#pragma unroll
    for (int i = 0; i < 8; i++)
#pragma unroll
        for (int j = 0; j < 8; j++) acc[i][j] = 0.f;

    for (int k0 = 0; k0 < DIM; k0 += BK) {
        float4 av = arow ? *(const float4*)(arow + k0 + lk * 4) : make_float4(0.f, 0.f, 0.f, 0.f);
        float4 bv = *(const float4*)(brow + k0 + lk * 4);
        As[lk * 4 + 0][lm] = av.x; As[lk * 4 + 1][lm] = av.y;
        As[lk * 4 + 2][lm] = av.z; As[lk * 4 + 3][lm] = av.w;
        Bs[lk * 4 + 0][lm] = bv.x; Bs[lk * 4 + 1][lm] = bv.y;
        Bs[lk * 4 + 2][lm] = bv.z; Bs[lk * 4 + 3][lm] = bv.w;
        __syncthreads();
#pragma unroll
        for (int kk = 0; kk < BK; kk++) {
            float4 a0 = *(const float4*)&As[kk][ty * 4];
            float4 a1 = *(const float4*)&As[kk][64 + ty * 4];
            float4 b0 = *(const float4*)&Bs[kk][tx * 4];
            float4 b1 = *(const float4*)&Bs[kk][64 + tx * 4];
            float ar[8] = {a0.x, a0.y, a0.z, a0.w, a1.x, a1.y, a1.z, a1.w};
            float br[8] = {b0.x, b0.y, b0.z, b0.w, b1.x, b1.y, b1.z, b1.w};
#pragma unroll
            for (int i = 0; i < 8; i++)
#pragma unroll
                for (int j = 0; j < 8; j++) acc[i][j] += ar[i] * br[j];
        }
        __syncthreads();
    }
    float4 bb0 = *(const float4*)&bias[(size_t)e * FF + n0 + tx * 4];
    float4 bb1 = *(const float4*)&bias[(size_t)e * FF + n0 + 64 + tx * 4];
    float bb[8] = {bb0.x, bb0.y, bb0.z, bb0.w, bb1.x, bb1.y, bb1.z, bb1.w};
#pragma unroll
    for (int i = 0; i < 8; i++) {
        int m = rstart + ((i < 4) ? (ty * 4 + i) : (64 + ty * 4 + i - 4));
        size_t off = (size_t)m * FF;
        float4 o0, o1;
        o0.x = gelu_exact(acc[i][0] + bb[0]); o0.y = gelu_exact(acc[i][1] + bb[1]);
        o0.z = gelu_exact(acc[i][2] + bb[2]); o0.w = gelu_exact(acc[i][3] + bb[3]);
        o1.x = gelu_exact(acc[i][4] + bb[4]); o1.y = gelu_exact(acc[i][5] + bb[5]);
        o1.z = gelu_exact(acc[i][6] + bb[6]); o1.w = gelu_exact(acc[i][7] + bb[7]);
        *(float4*)&g_H[off + n0 + tx * 4]      = o0;
        *(float4*)&g_H[off + n0 + 64 + tx * 4] = o1;
    }
}

// ---------------- routed fc2 ----------------
__global__ __launch_bounds__(256, 2) void fc2_kernel(const float* __restrict__ w,
                                                     const float* __restrict__ bias) {
    int rstart = blockIdx.x * BM;
    if (rstart >= g_base[NE]) return;
    int e = 0;
#pragma unroll
    for (int i = 0; i < NE; i++) if (rstart >= g_base[i + 1]) e = i + 1;
    const float* We = w + (size_t)e * DIM * FF;
    int n0 = blockIdx.y * BN;
    __shared__ float As[BK][BM];
    __shared__ float Bs[BK][BN];
    int tid = threadIdx.x;
    int lm = tid & 127, lk = tid >> 7;
    const float* arow = g_H + (size_t)(rstart + lm) * FF;
    const float* brow = We + (size_t)(n0 + lm) * FF;
    int tx = tid & 15, ty = tid >> 4;
    float acc[8][8];
#pragma unroll
    for (int i = 0; i < 8; i++)
#pragma unroll
        for (int j = 0; j < 8; j++) acc[i][j] = 0.f;

    for (int k0 = 0; k0 < FF; k0 += BK) {
        float4 av = *(const float4*)(arow + k0 + lk * 4);
        float4 bv = *(const float4*)(brow + k0 + lk * 4);
        As[lk * 4 + 0][lm] = av.x; As[lk * 4 + 1][lm] = av.y;
        As[lk * 4 + 2][lm] = av.z; As[lk * 4 + 3][lm] = av.w;
        Bs[lk * 4 + 0][lm] = bv.x; Bs[lk * 4 + 1][lm] = bv.y;
        Bs[lk * 4 + 2][lm] = bv.z; Bs[lk * 4 + 3][lm] = bv.w;
        __syncthreads();
#pragma unroll
        for (int kk = 0; kk < BK; kk++) {
            float4 a0 = *(const float4*)&As[kk][ty * 4];
            float4 a1 = *(const float4*)&As[kk][64 + ty * 4];
            float4 b0 = *(const float4*)&Bs[kk][tx * 4];
            float4 b1 = *(const float4*)&Bs[kk][64 + tx * 4];
            float ar[8] = {a0.x, a0.y, a0.z, a0.w, a1.x, a1.y, a1.z, a1.w};
            float br[8] = {b0.x, b0.y, b0.z, b0.w, b1.x, b1.y, b1.z, b1.w};
#pragma unroll
            for (int i = 0; i < 8; i++)
#pragma unroll
                for (int j = 0; j < 8; j++) acc[i][j] += ar[i] * br[j];
        }
        __syncthreads();
    }
    float4 bb0 = *(const float4*)&bias[(size_t)e * DIM + n0 + tx * 4];
    float4 bb1 = *(const float4*)&bias[(size_t)e * DIM + n0 + 64 + tx * 4];
    float bb[8] = {bb0.x, bb0.y, bb0.z, bb0.w, bb1.x, bb1.y, bb1.z, bb1.w};
#pragma unroll
    for (int i = 0; i < 8; i++) {
        int m = rstart + ((i < 4) ? (ty * 4 + i) : (64 + ty * 4 + i - 4));
        size_t off = (size_t)m * DIM;
        float4 o0, o1;
        o0.x = acc[i][0] + bb[0]; o0.y = acc[i][1] + bb[1];
        o0.z = acc[i][2] + bb[2]; o0.w = acc[i][3] + bb[3];
        o1.x = acc[i][4] + bb[4]; o1.y = acc[i][5] + bb[5];
        o1.z = acc[i][6] + bb[6]; o1.w = acc[i][7] + bb[7];
        *(float4*)&g_Y[off + n0 + tx * 4]      = o0;
        *(float4*)&g_Y[off + n0 + 64 + tx * 4] = o1;
    }
}

// ---------------- dense GEMM: C[m][n] = A[m][:] . B[n][:] + bias[n] ----------------
// asel: 0 -> A = x (param), 1 -> A = g_G
// csel: 0 -> C = g_G, 1 -> C = g_G3, 2 -> C = out (param)
__global__ __launch_bounds__(256, 2) void dense_gemm_kernel(const float* __restrict__ X,
                                                            const float* __restrict__ B,
                                                            const float* __restrict__ bias,
                                                            float* __restrict__ OUT,
                                                            int K, int N, int asel, int csel) {
    const float* A = (asel == 0) ? X : g_G;
    float* C = (csel == 0) ? g_G : ((csel == 1) ? g_G3 : OUT);
    int m0 = blockIdx.x * BM, n0 = blockIdx.y * BN;
    __shared__ float As[BK][BM];
    __shared__ float Bs[BK][BN];
    int tid = threadIdx.x;
    int lm = tid & 127, lk = tid >> 7;
    const float* arow = A + (size_t)(m0 + lm) * K;
    const float* brow = B + (size_t)(n0 + lm) * K;
    int tx = tid & 15, ty = tid >> 4;
    float acc[8][8];
#pragma unroll
    for (int i = 0; i < 8; i++)
#pragma unroll
        for (int j = 0; j < 8; j++) acc[i][j] = 0.f;

    for (int k0 = 0; k0 < K; k0 += BK) {
        float4 av = *(const float4*)(arow + k0 + lk * 4);
        float4 bv = *(const float4*)(brow + k0 + lk * 4);
        As[lk * 4 + 0][lm] = av.x; As[lk * 4 + 1][lm] = av.y;
        As[lk * 4 + 2][lm] = av.z; As[lk * 4 + 3][lm] = av.w;
        Bs[lk * 4 + 0][lm] = bv.x; Bs[lk * 4 + 1][lm] = bv.y;
        Bs[lk * 4 + 2][lm] = bv.z; Bs[lk * 4 + 3][lm] = bv.w;
        __syncthreads();
#pragma unroll
        for (int kk = 0; kk < BK; kk++) {
            float4 a0 = *(const float4*)&As[kk][ty * 4];
            float4 a1 = *(const float4*)&As[kk][64 + ty * 4];
            float4 b0 = *(const float4*)&Bs[kk][tx * 4];
            float4 b1 = *(const float4*)&Bs[kk][64 + tx * 4];
            float ar[8] = {a0.x, a0.y, a0.z, a0.w, a1.x, a1.y, a1.z, a1.w};
            float br[8] = {b0.x, b0.y, b0.z, b0.w, b1.x, b1.y, b1.z, b1.w};
#pragma unroll
            for (int i = 0; i < 8; i++)
#pragma unroll
                for (int j = 0; j < 8; j++) acc[i][j] += ar[i] * br[j];
        }
        __syncthreads();
    }
    float4 bb0 = *(const float4*)&bias[n0 + tx * 4];
    float4 bb1 = *(const float4*)&bias[n0 + 64 + tx * 4];
    float bb[8] = {bb0.x, bb0.y, bb0.z, bb0.w, bb1.x, bb1.y, bb1.z, bb1.w};
#pragma unroll
    for (int i = 0; i < 8; i++) {
        int m = m0 + ((i < 4) ? (ty * 4 + i) : (64 + ty * 4 + i - 4));
        size_t off = (size_t)m * N;
        float4 o0, o1;
        o0.x = acc[i][0] + bb[0]; o0.y = acc[i][1] + bb[1];
        o0.z = acc[i][2] + bb[2]; o0.w = acc[i][3] + bb[3];
        o1.x = acc[i][4] + bb[4]; o1.y = acc[i][5] + bb[5];
        o1.z = acc[i][6] + bb[6]; o1.w = acc[i][7] + bb[7];
        *(float4*)&C[off + n0 + tx * 4]      = o0;
        *(float4*)&C[off + n0 + 64 + tx * 4] = o1;
    }
}

// ---------------- elementwise: g_G = gelu(g_G) * g_G3 ----------------
__global__ void gated_eltwise_kernel() {
    size_t i = (size_t)blockIdx.x * blockDim.x + threadIdx.x;
    if (i >= (size_t)T_TOK * FF) return;
    g_G[i] = gelu_exact(g_G[i]) * g_G3[i];
}

// ---------------- combine: out += w0*Y[row0] + w1*Y[row1] ----------------
__global__ void combine_kernel(float* __restrict__ out) {
    size_t i = (size_t)blockIdx.x * blockDim.x + threadIdx.x;
    if (i >= (size_t)T_TOK * DIM) return;
    int t = (int)(i / DIM), c = (int)(i % DIM);
    float v = out[i];
    int r0 = g_rowmap[2 * t], r1 = g_rowmap[2 * t + 1];
    v += g_slotw[2 * t]     * g_Y[(size_t)r0 * DIM + c];
    v += g_slotw[2 * t + 1] * g_Y[(size_t)r1 * DIM + c];
    out[i] = v;
}

// ---------------- launch ----------------
extern "C" void kernel_launch(void* const* d_in, const int* in_sizes, int n_in,
                              void* d_out, int out_size) {
    const float* x      = (const float*)d_in[0];
    const float* gate_w = (const float*)d_in[1];
    const float* fc1_w  = (const float*)d_in[2];
    const float* fc1_b  = (const float*)d_in[3];
    const float* fc2_w  = (const float*)d_in[4];
    const float* fc2_b  = (const float*)d_in[5];
    const float* w1_w   = (const float*)d_in[6];
    const float* w1_b   = (const float*)d_in[7];
    const float* w3_w   = (const float*)d_in[8];
    const float* w3_b   = (const float*)d_in[9];
    const float* w2_w   = (const float*)d_in[10];
    const float* w2_b   = (const float*)d_in[11];
    float* out = (float*)d_out;

    init_kernel<<<(ROWS_PAD_MAX + 255) / 256, 256>>>();
    gate_kernel<<<T_TOK / 8, 256>>>(x, gate_w);
    scan_kernel<<<1, 32>>>();
    assign_kernel<<<(T_TOK + 255) / 256, 256>>>();

    // routed experts
    fc1_kernel<<<dim3(ROW_TILES, FF / BN), 256>>>(x, fc1_w, fc1_b);
    fc2_kernel<<<dim3(ROW_TILES, DIM / BN), 256>>>(fc2_w, fc2_b);

    // shared gated MLP
    dense_gemm_kernel<<<dim3(T_TOK / BM, FF / BN), 256>>>(x, w1_w, w1_b, out, DIM, FF, 0, 0);
    dense_gemm_kernel<<<dim3(T_TOK / BM, FF / BN), 256>>>(x, w3_w, w3_b, out, DIM, FF, 0, 1);
    gated_eltwise_kernel<<<(int)(((size_t)T_TOK * FF + 255) / 256), 256>>>();
    dense_gemm_kernel<<<dim3(T_TOK / BM, DIM / BN), 256>>>(x, w2_w, w2_b, out, FF, DIM, 1, 2);

    // final combine (deterministic gather, no atomics into out)
    combine_kernel<<<(int)(((size_t)T_TOK * DIM + 255) / 256), 256>>>(out);
}

// round 5
// speedup vs baseline: 2.5090x; 2.5090x over previous
#include <cuda_runtime.h>
#include <cuda_bf16.h>
#include <math.h>
#include <stdint.h>

// ---------------- problem constants ----------------
#define T_TOK   16384
#define DIM     768
#define FF      2048
#define NE      8
#define SLOTS   (2*T_TOK)
#define BM      128
#define ROWS_PAD_MAX (SLOTS + NE*BM)   // 33792
#define ROW_TILES    (ROWS_PAD_MAX/BM) // 264

// GEMM tiling
#define GBM 128
#define GBN 128
#define GBK 32                  // K elements per stage chunk (64 bytes/row bf16)
#define ROWB 80                 // padded row stride in bytes (64 data + 16 pad)
#define MATB (128*ROWB)         // 10240 bytes per matrix per stage
#define STAGEB (4*MATB)         // 40960: Ahi, Alo, Bhi, Blo
#define SM_BIAS (2*STAGEB)      // 81920
#define SM_TOTAL (2*STAGEB + 512)

// ---------------- device scratch ----------------
__device__ __nv_bfloat16 g_xhi [(size_t)T_TOK * DIM];
__device__ __nv_bfloat16 g_xlo [(size_t)T_TOK * DIM];
__device__ __nv_bfloat16 g_f1hi[(size_t)NE * FF * DIM];
__device__ __nv_bfloat16 g_f1lo[(size_t)NE * FF * DIM];
__device__ __nv_bfloat16 g_f2hi[(size_t)NE * DIM * FF];
__device__ __nv_bfloat16 g_f2lo[(size_t)NE * DIM * FF];
__device__ __nv_bfloat16 g_w1hi[(size_t)FF * DIM];
__device__ __nv_bfloat16 g_w1lo[(size_t)FF * DIM];
__device__ __nv_bfloat16 g_w3hi[(size_t)FF * DIM];
__device__ __nv_bfloat16 g_w3lo[(size_t)FF * DIM];
__device__ __nv_bfloat16 g_w2hi[(size_t)DIM * FF];
__device__ __nv_bfloat16 g_w2lo[(size_t)DIM * FF];
__device__ __nv_bfloat16 g_Hhi [(size_t)ROWS_PAD_MAX * FF];
__device__ __nv_bfloat16 g_Hlo [(size_t)ROWS_PAD_MAX * FF];
__device__ __nv_bfloat16 g_Ghi [(size_t)T_TOK * FF];
__device__ __nv_bfloat16 g_Glo [(size_t)T_TOK * FF];
__device__ float g_G [(size_t)T_TOK * FF];
__device__ float g_G3[(size_t)T_TOK * FF];
__device__ float g_Y [(size_t)ROWS_PAD_MAX * DIM];
__device__ int   g_rowtoken[ROWS_PAD_MAX];
__device__ int   g_rowmap[SLOTS];
__device__ float g_slotw[SLOTS];
__device__ int   g_slote[SLOTS];
__device__ int   g_counts[NE];
__device__ int   g_cursor[NE];
__device__ int   g_base[NE+1];

__device__ __forceinline__ float gelu_exact(float v) {
    return 0.5f * v * (1.0f + erff(v * 0.7071067811865475f));
}

// ---------------- PTX helpers (sm_80+ portable) ----------------
__device__ __forceinline__ uint32_t smem_u32(const void* p) {
    uint32_t a;
    asm("{ .reg .u64 t; cvta.to.shared.u64 t, %1; cvt.u32.u64 %0, t; }" : "=r"(a) : "l"(p));
    return a;
}
#define CP16(sa, gp) asm volatile("cp.async.cg.shared.global [%0], [%1], 16;" :: "r"(sa), "l"(gp))
#define CP_COMMIT()  asm volatile("cp.async.commit_group;" ::: "memory")
#define CP_WAIT1()   asm volatile("cp.async.wait_group 1;" ::: "memory")

__device__ __forceinline__ void mma_bf16(float* c, const uint32_t* a, const uint32_t* b) {
    asm volatile(
        "mma.sync.aligned.m16n8k16.row.col.f32.bf16.bf16.f32 "
        "{%0,%1,%2,%3}, {%4,%5,%6,%7}, {%8,%9}, {%0,%1,%2,%3};"
        : "+f"(c[0]), "+f"(c[1]), "+f"(c[2]), "+f"(c[3])
        : "r"(a[0]), "r"(a[1]), "r"(a[2]), "r"(a[3]), "r"(b[0]), "r"(b[1]));
}

// ---------------- small kernels ----------------
__global__ void init_kernel() {
    int i = blockIdx.x * blockDim.x + threadIdx.x;
    if (i < ROWS_PAD_MAX) g_rowtoken[i] = -1;
    if (i < NE) { g_counts[i] = 0; g_cursor[i] = 0; }
}

__global__ __launch_bounds__(256) void gate_kernel(const float* __restrict__ x,
                                                   const float* __restrict__ gw) {
    __shared__ float sgw[NE * DIM];
    for (int i = threadIdx.x; i < NE * DIM; i += 256) sgw[i] = gw[i];
    __syncthreads();
    int warp = threadIdx.x >> 5, lane = threadIdx.x & 31;
    int t = blockIdx.x * 8 + warp;
    if (t >= T_TOK) return;
    const float* xr = x + (size_t)t * DIM;
    float xv[24];
#pragma unroll
    for (int j = 0; j < 24; j++) xv[j] = xr[lane + 32 * j];
    float logit[NE];
#pragma unroll
    for (int e = 0; e < NE; e++) {
        float p = 0.f;
#pragma unroll
        for (int j = 0; j < 24; j++) p += xv[j] * sgw[e * DIM + lane + 32 * j];
#pragma unroll
        for (int off = 16; off > 0; off >>= 1) p += __shfl_down_sync(0xffffffffu, p, off);
        logit[e] = p;
    }
    if (lane == 0) {
        float m = logit[0];
#pragma unroll
        for (int e = 1; e < NE; e++) m = fmaxf(m, logit[e]);
        int a = 0;
#pragma unroll
        for (int e = 1; e < NE; e++) if (logit[e] > logit[a]) a = e;
        int b = (a == 0) ? 1 : 0;
#pragma unroll
        for (int e = 0; e < NE; e++) { if (e == a || e == b) continue; if (logit[e] > logit[b]) b = e; }
        float pa = expf(logit[a] - m), pb = expf(logit[b] - m);
        float inv = 1.f / (pa + pb);
        g_slote[2 * t] = a;  g_slote[2 * t + 1] = b;
        g_slotw[2 * t] = pa * inv;  g_slotw[2 * t + 1] = pb * inv;
        atomicAdd(&g_counts[a], 1);
        atomicAdd(&g_counts[b], 1);
    }
}

__global__ void scan_kernel() {
    if (threadIdx.x == 0 && blockIdx.x == 0) {
        int b = 0; g_base[0] = 0;
        for (int e = 0; e < NE; e++) {
            b += ((g_counts[e] + BM - 1) / BM) * BM;
            g_base[e + 1] = b;
        }
    }
}

__global__ void assign_kernel() {
    int t = blockIdx.x * blockDim.x + threadIdx.x;
    if (t >= T_TOK) return;
#pragma unroll
    for (int k = 0; k < 2; k++) {
        int e = g_slote[2 * t + k];
        int pos = atomicAdd(&g_cursor[e], 1);
        int row = g_base[e] + pos;
        g_rowmap[2 * t + k] = row;
        g_rowtoken[row] = t;
    }
}

// fp32 -> bf16 hi/lo split (vectorized by 4)
__global__ void split_kernel(const float* __restrict__ s,
                             __nv_bfloat16* __restrict__ hi,
                             __nv_bfloat16* __restrict__ lo, int n4) {
    int i = blockIdx.x * blockDim.x + threadIdx.x;
    if (i >= n4) return;
    float4 v = ((const float4*)s)[i];
    float vv[4] = {v.x, v.y, v.z, v.w};
    __nv_bfloat16 h[4], l[4];
#pragma unroll
    for (int j = 0; j < 4; j++) {
        h[j] = __float2bfloat16(vv[j]);
        l[j] = __float2bfloat16(vv[j] - __bfloat162float(h[j]));
    }
    ((uint2*)hi)[i] = *(uint2*)h;
    ((uint2*)lo)[i] = *(uint2*)l;
}

// gated eltwise: prod = gelu(g_G) * g_G3 -> split to g_Ghi/g_Glo
__global__ void gated_eltwise_kernel() {
    int i = blockIdx.x * blockDim.x + threadIdx.x;
    int n4 = (int)((size_t)T_TOK * FF / 4);
    if (i >= n4) return;
    float4 a = ((const float4*)g_G)[i];
    float4 b = ((const float4*)g_G3)[i];
    float p[4];
    p[0] = gelu_exact(a.x) * b.x;
    p[1] = gelu_exact(a.y) * b.y;
    p[2] = gelu_exact(a.z) * b.z;
    p[3] = gelu_exact(a.w) * b.w;
    __nv_bfloat16 h[4], l[4];
#pragma unroll
    for (int j = 0; j < 4; j++) {
        h[j] = __float2bfloat16(p[j]);
        l[j] = __float2bfloat16(p[j] - __bfloat162float(h[j]));
    }
    ((uint2*)g_Ghi)[i] = *(uint2*)h;
    ((uint2*)g_Glo)[i] = *(uint2*)l;
}

__global__ void combine_kernel(float* __restrict__ out) {
    size_t i = (size_t)blockIdx.x * blockDim.x + threadIdx.x;
    if (i >= (size_t)T_TOK * DIM) return;
    int t = (int)(i / DIM), c = (int)(i % DIM);
    float v = out[i];
    int r0 = g_rowmap[2 * t], r1 = g_rowmap[2 * t + 1];
    v += g_slotw[2 * t]     * g_Y[(size_t)r0 * DIM + c];
    v += g_slotw[2 * t + 1] * g_Y[(size_t)r1 * DIM + c];
    out[i] = v;
}

// ---------------- mma.sync split-bf16 GEMM ----------------
// C[M,N] = (Ahi+Alo)[M,K] x (Bhi+Blo)[N,K]^T + bias   (lo*lo dropped)
// MODE 0: gelu(acc+bias) -> bf16 hi/lo pair (Chi, Clo)
// MODE 1: acc+bias -> fp32 Cf
template<int MODE>
__global__ __launch_bounds__(256, 2) void mma_gemm_kernel(
    const __nv_bfloat16* __restrict__ Ahi, const __nv_bfloat16* __restrict__ Alo,
    const __nv_bfloat16* __restrict__ Bhi, const __nv_bfloat16* __restrict__ Blo,
    const float* __restrict__ bias,
    float* __restrict__ Cf,
    __nv_bfloat16* __restrict__ Chi, __nv_bfloat16* __restrict__ Clo,
    int K, int N, int expert_mode, int gather)
{
    extern __shared__ char smem[];
    uint32_t sb = smem_u32(smem);
    int tid = threadIdx.x;

    int rstart = blockIdx.x * GBM;
    int n0 = blockIdx.y * GBN;

    if (expert_mode) {
        if (rstart >= g_base[NE]) return;
        int e = 0;
#pragma unroll
        for (int i = 0; i < NE; i++) if (rstart >= g_base[i + 1]) e = i + 1;
        size_t wo = (size_t)e * N * K;
        Bhi += wo; Blo += wo;
        bias += (size_t)e * N;
    }

    // ---- per-thread load assignment: thread t loads row t/2, 32B half (t&1) ----
    int lrow = tid >> 1;
    int lcb  = (tid & 1) * 32;
    int arow_g;
    if (gather) {
        int tok = g_rowtoken[rstart + lrow];
        arow_g = (tok < 0) ? 0 : tok;
        if (!0) {} // keep shape
    } else {
        arow_g = rstart + lrow;
    }
    const char* pAh = (const char*)(Ahi + (size_t)arow_g * K) + lcb;
    const char* pAl = (const char*)(Alo + (size_t)arow_g * K) + lcb;
    const char* pBh = (const char*)(Bhi + (size_t)(n0 + lrow) * K) + lcb;
    const char* pBl = (const char*)(Blo + (size_t)(n0 + lrow) * K) + lcb;
    uint32_t sA = sb + (uint32_t)(lrow * ROWB + lcb);

    if (tid < 128) ((float*)(smem + SM_BIAS))[tid] = bias[n0 + tid];

    int nk = K / GBK;

#define ISSUE(kc, s) do { \
    uint32_t o = (uint32_t)(s) * STAGEB; \
    size_t g = (size_t)(kc) * 64; \
    CP16(sA + o,              pAh + g); CP16(sA + o + 16,            pAh + g + 16); \
    CP16(sA + o + MATB,       pAl + g); CP16(sA + o + MATB + 16,     pAl + g + 16); \
    CP16(sA + o + 2*MATB,     pBh + g); CP16(sA + o + 2*MATB + 16,   pBh + g + 16); \
    CP16(sA + o + 3*MATB,     pBl + g); CP16(sA + o + 3*MATB + 16,   pBl + g + 16); \
    CP_COMMIT(); } while (0)

    ISSUE(0, 0);
    ISSUE(1, 1);

    int wid = tid >> 5, lane = tid & 31;
    int wm = (wid & 3) * 32;        // warp M offset (32 rows)
    int wn = (wid >> 2) * 64;       // warp N offset (64 cols)
    int lq = lane >> 2;             // 0..7
    int lr = lane & 3;              // 0..3

    float acc[2][8][4];
#pragma unroll
    for (int m = 0; m < 2; m++)
#pragma unroll
        for (int n = 0; n < 8; n++)
#pragma unroll
            for (int j = 0; j < 4; j++) acc[m][n][j] = 0.f;

    for (int kc = 0; kc < nk; kc++) {
        CP_WAIT1();
        __syncthreads();
        const char* s0 = smem + (size_t)(kc & 1) * STAGEB;
#pragma unroll
        for (int ks = 0; ks < 2; ks++) {
            int kb = ks * 32 + lr * 4;
            uint32_t ah[2][4], al[2][4];
#pragma unroll
            for (int m = 0; m < 2; m++) {
                const char* pa = s0 + (wm + m * 16 + lq) * ROWB + kb;
                ah[m][0] = *(const uint32_t*)(pa);
                ah[m][1] = *(const uint32_t*)(pa + 8 * ROWB);
                ah[m][2] = *(const uint32_t*)(pa + 16);
                ah[m][3] = *(const uint32_t*)(pa + 8 * ROWB + 16);
                const char* pl = pa + MATB;
                al[m][0] = *(const uint32_t*)(pl);
                al[m][1] = *(const uint32_t*)(pl + 8 * ROWB);
                al[m][2] = *(const uint32_t*)(pl + 16);
                al[m][3] = *(const uint32_t*)(pl + 8 * ROWB + 16);
            }
#pragma unroll
            for (int n = 0; n < 8; n++) {
                const char* pb = s0 + 2 * MATB + (wn + n * 8 + lq) * ROWB + kb;
                uint32_t bh[2], bl[2];
                bh[0] = *(const uint32_t*)(pb);
                bh[1] = *(const uint32_t*)(pb + 16);
                bl[0] = *(const uint32_t*)(pb + MATB);
                bl[1] = *(const uint32_t*)(pb + MATB + 16);
#pragma unroll
                for (int m = 0; m < 2; m++) {
                    mma_bf16(acc[m][n], ah[m], bh);
                    mma_bf16(acc[m][n], ah[m], bl);
                    mma_bf16(acc[m][n], al[m], bh);
                }
            }
        }
        __syncthreads();
        if (kc + 2 < nk) { ISSUE(kc + 2, kc & 1); }
        else { CP_COMMIT(); }
    }
#undef ISSUE

    // ---- epilogue: registers -> global ----
    const float* sbias = (const float*)(smem + SM_BIAS);
#pragma unroll
    for (int m = 0; m < 2; m++) {
        int r0 = rstart + wm + m * 16 + lq;
#pragma unroll
        for (int n = 0; n < 8; n++) {
            int col = wn + n * 8 + lr * 2;
            float b0 = sbias[col], b1 = sbias[col + 1];
            int gc = n0 + col;
            float v00 = acc[m][n][0] + b0, v01 = acc[m][n][1] + b1;
            float v10 = acc[m][n][2] + b0, v11 = acc[m][n][3] + b1;
            if (MODE == 1) {
                float2 o0 = make_float2(v00, v01);
                float2 o1 = make_float2(v10, v11);
                *(float2*)&Cf[(size_t)r0 * N + gc]       = o0;
                *(float2*)&Cf[(size_t)(r0 + 8) * N + gc] = o1;
            } else {
                float g00 = gelu_exact(v00), g01 = gelu_exact(v01);
                float g10 = gelu_exact(v10), g11 = gelu_exact(v11);
                __nv_bfloat162 h0, h1, l0, l1;
                h0.x = __float2bfloat16(g00); h0.y = __float2bfloat16(g01);
                h1.x = __float2bfloat16(g10); h1.y = __float2bfloat16(g11);
                l0.x = __float2bfloat16(g00 - __bfloat162float(h0.x));
                l0.y = __float2bfloat16(g01 - __bfloat162float(h0.y));
                l1.x = __float2bfloat16(g10 - __bfloat162float(h1.x));
                l1.y = __float2bfloat16(g11 - __bfloat162float(h1.y));
                *(__nv_bfloat162*)&Chi[(size_t)r0 * N + gc]       = h0;
                *(__nv_bfloat162*)&Chi[(size_t)(r0 + 8) * N + gc] = h1;
                *(__nv_bfloat162*)&Clo[(size_t)r0 * N + gc]       = l0;
                *(__nv_bfloat162*)&Clo[(size_t)(r0 + 8) * N + gc] = l1;
            }
        }
    }
}

// ---------------- launch ----------------
extern "C" void kernel_launch(void* const* d_in, const int* in_sizes, int n_in,
                              void* d_out, int out_size) {
    const float* x      = (const float*)d_in[0];
    const float* gate_w = (const float*)d_in[1];
    const float* fc1_w  = (const float*)d_in[2];
    const float* fc1_b  = (const float*)d_in[3];
    const float* fc2_w  = (const float*)d_in[4];
    const float* fc2_b  = (const float*)d_in[5];
    const float* w1_w   = (const float*)d_in[6];
    const float* w1_b   = (const float*)d_in[7];
    const float* w3_w   = (const float*)d_in[8];
    const float* w3_b   = (const float*)d_in[9];
    const float* w2_w   = (const float*)d_in[10];
    const float* w2_b   = (const float*)d_in[11];
    float* out = (float*)d_out;

    cudaFuncSetAttribute(mma_gemm_kernel<0>, cudaFuncAttributeMaxDynamicSharedMemorySize, SM_TOTAL);
    cudaFuncSetAttribute(mma_gemm_kernel<1>, cudaFuncAttributeMaxDynamicSharedMemorySize, SM_TOTAL);

    // routing metadata
    init_kernel<<<(ROWS_PAD_MAX + 255) / 256, 256>>>();
    gate_kernel<<<T_TOK / 8, 256>>>(x, gate_w);
    scan_kernel<<<1, 32>>>();
    assign_kernel<<<(T_TOK + 255) / 256, 256>>>();

    // bf16 hi/lo splits
    __nv_bfloat16* xhi;  cudaGetSymbolAddress((void**)&xhi,  g_xhi);
    __nv_bfloat16* xlo;  cudaGetSymbolAddress((void**)&xlo,  g_xlo);
    __nv_bfloat16* f1hi; cudaGetSymbolAddress((void**)&f1hi, g_f1hi);
    __nv_bfloat16* f1lo; cudaGetSymbolAddress((void**)&f1lo, g_f1lo);
    __nv_bfloat16* f2hi; cudaGetSymbolAddress((void**)&f2hi, g_f2hi);
    __nv_bfloat16* f2lo; cudaGetSymbolAddress((void**)&f2lo, g_f2lo);
    __nv_bfloat16* w1hi; cudaGetSymbolAddress((void**)&w1hi, g_w1hi);
    __nv_bfloat16* w1lo; cudaGetSymbolAddress((void**)&w1lo, g_w1lo);
    __nv_bfloat16* w3hi; cudaGetSymbolAddress((void**)&w3hi, g_w3hi);
    __nv_bfloat16* w3lo; cudaGetSymbolAddress((void**)&w3lo, g_w3lo);
    __nv_bfloat16* w2hi; cudaGetSymbolAddress((void**)&w2hi, g_w2hi);
    __nv_bfloat16* w2lo; cudaGetSymbolAddress((void**)&w2lo, g_w2lo);
    __nv_bfloat16* Hhi;  cudaGetSymbolAddress((void**)&Hhi,  g_Hhi);
    __nv_bfloat16* Hlo;  cudaGetSymbolAddress((void**)&Hlo,  g_Hlo);
    __nv_bfloat16* Ghi;  cudaGetSymbolAddress((void**)&Ghi,  g_Ghi);
    __nv_bfloat16* Glo;  cudaGetSymbolAddress((void**)&Glo,  g_Glo);
    float* Gf;  cudaGetSymbolAddress((void**)&Gf,  g_G);
    float* G3f; cudaGetSymbolAddress((void**)&G3f, g_G3);
    float* Yf;  cudaGetSymbolAddress((void**)&Yf,  g_Y);

    auto split = [&](const float* s, __nv_bfloat16* hi, __nv_bfloat16* lo, size_t n) {
        int n4 = (int)(n / 4);
        split_kernel<<<(n4 + 255) / 256, 256>>>(s, hi, lo, n4);
    };
    split(x,     xhi,  xlo,  (size_t)T_TOK * DIM);
    split(fc1_w, f1hi, f1lo, (size_t)NE * FF * DIM);
    split(fc2_w, f2hi, f2lo, (size_t)NE * DIM * FF);
    split(w1_w,  w1hi, w1lo, (size_t)FF * DIM);
    split(w3_w,  w3hi, w3lo, (size_t)FF * DIM);
    split(w2_w,  w2hi, w2lo, (size_t)DIM * FF);

    // routed experts
    mma_gemm_kernel<0><<<dim3(ROW_TILES, FF / GBN), 256, SM_TOTAL>>>(
        xhi, xlo, f1hi, f1lo, fc1_b, nullptr, Hhi, Hlo, DIM, FF, 1, 1);
    mma_gemm_kernel<1><<<dim3(ROW_TILES, DIM / GBN), 256, SM_TOTAL>>>(
        Hhi, Hlo, f2hi, f2lo, fc2_b, Yf, nullptr, nullptr, FF, DIM, 1, 0);

    // shared gated MLP
    mma_gemm_kernel<1><<<dim3(T_TOK / GBM, FF / GBN), 256, SM_TOTAL>>>(
        xhi, xlo, w1hi, w1lo, w1_b, Gf, nullptr, nullptr, DIM, FF, 0, 0);
    mma_gemm_kernel<1><<<dim3(T_TOK / GBM, FF / GBN), 256, SM_TOTAL>>>(
        xhi, xlo, w3hi, w3lo, w3_b, G3f, nullptr, nullptr, DIM, FF, 0, 0);
    gated_eltwise_kernel<<<(int)(((size_t)T_TOK * FF / 4 + 255) / 256), 256>>>();
    mma_gemm_kernel<1><<<dim3(T_TOK / GBM, DIM / GBN), 256, SM_TOTAL>>>(
        Ghi, Glo, w2hi, w2lo, w2_b, out, nullptr, nullptr, FF, DIM, 0, 0);

    // combine
    combine_kernel<<<(int)(((size_t)T_TOK * DIM + 255) / 256), 256>>>(out);
}

// round 6
// speedup vs baseline: 3.4628x; 1.3802x over previous
#include <cuda_runtime.h>
#include <cuda_fp16.h>
#include <math.h>
#include <stdint.h>

// ---------------- problem constants ----------------
#define T_TOK   16384
#define DIM     768
#define FF      2048
#define NE      8
#define SLOTS   (2*T_TOK)
#define BM      128
#define ROWS_PAD_MAX (SLOTS + NE*BM)   // 33792
#define ROW_TILES    (ROWS_PAD_MAX/BM) // 264

// GEMM tiling
#define GBM 128
#define GBN 128
#define GBK 32                  // K elements per stage chunk (64 bytes/row fp16)
#define ROWB 80                 // padded row stride bytes (64 data + 16 pad)
#define MATB (128*ROWB)         // 10240 bytes per matrix per stage
#define STAGEB (3*MATB)         // 30720: A, Bhi, Blo
#define STAGES 3
#define SM_BIAS (STAGES*STAGEB) // 92160
#define SM_TOTAL (SM_BIAS + 512)

// ---------------- device scratch ----------------
__device__ __half g_xh [(size_t)T_TOK * DIM];
__device__ __half g_f1h[(size_t)NE * FF * DIM];
__device__ __half g_f1l[(size_t)NE * FF * DIM];
__device__ __half g_f2h[(size_t)NE * DIM * FF];
__device__ __half g_f2l[(size_t)NE * DIM * FF];
__device__ __half g_w1h[(size_t)FF * DIM];
__device__ __half g_w1l[(size_t)FF * DIM];
__device__ __half g_w3h[(size_t)FF * DIM];
__device__ __half g_w3l[(size_t)FF * DIM];
__device__ __half g_w2h[(size_t)DIM * FF];
__device__ __half g_w2l[(size_t)DIM * FF];
__device__ __half g_H  [(size_t)ROWS_PAD_MAX * FF];
__device__ __half g_Gp [(size_t)T_TOK * FF];
__device__ float g_G [(size_t)T_TOK * FF];
__device__ float g_G3[(size_t)T_TOK * FF];
__device__ float g_Y [(size_t)ROWS_PAD_MAX * DIM];
__device__ int   g_rowtoken[ROWS_PAD_MAX];
__device__ int   g_rowmap[SLOTS];
__device__ float g_slotw[SLOTS];
__device__ int   g_slote[SLOTS];
__device__ int   g_counts[NE];
__device__ int   g_cursor[NE];
__device__ int   g_base[NE+1];

__device__ __forceinline__ float gelu_exact(float v) {
    return 0.5f * v * (1.0f + erff(v * 0.7071067811865475f));
}

// ---------------- PTX helpers (sm_80+ portable) ----------------
__device__ __forceinline__ uint32_t smem_u32(const void* p) {
    uint32_t a;
    asm("{ .reg .u64 t; cvta.to.shared.u64 t, %1; cvt.u32.u64 %0, t; }" : "=r"(a) : "l"(p));
    return a;
}
#define CP16(sa, gp) asm volatile("cp.async.cg.shared.global [%0], [%1], 16;" :: "r"(sa), "l"(gp))
#define CP_COMMIT()  asm volatile("cp.async.commit_group;" ::: "memory")
#define CP_WAIT2()   asm volatile("cp.async.wait_group 2;" ::: "memory")

#define LDSM4(r, a) \
    asm volatile("ldmatrix.sync.aligned.m8n8.x4.shared.b16 {%0,%1,%2,%3}, [%4];" \
        : "=r"((r)[0]), "=r"((r)[1]), "=r"((r)[2]), "=r"((r)[3]) : "r"(a))

__device__ __forceinline__ void mma_f16(float* c, const uint32_t* a, const uint32_t* b) {
    asm volatile(
        "mma.sync.aligned.m16n8k16.row.col.f32.f16.f16.f32 "
        "{%0,%1,%2,%3}, {%4,%5,%6,%7}, {%8,%9}, {%0,%1,%2,%3};"
        : "+f"(c[0]), "+f"(c[1]), "+f"(c[2]), "+f"(c[3])
        : "r"(a[0]), "r"(a[1]), "r"(a[2]), "r"(a[3]), "r"(b[0]), "r"(b[1]));
}

// ---------------- small kernels ----------------
__global__ void init_kernel() {
    int i = blockIdx.x * blockDim.x + threadIdx.x;
    if (i < ROWS_PAD_MAX) g_rowtoken[i] = -1;
    if (i < NE) { g_counts[i] = 0; g_cursor[i] = 0; }
}

__global__ __launch_bounds__(256) void gate_kernel(const float* __restrict__ x,
                                                   const float* __restrict__ gw) {
    __shared__ float sgw[NE * DIM];
    for (int i = threadIdx.x; i < NE * DIM; i += 256) sgw[i] = gw[i];
    __syncthreads();
    int warp = threadIdx.x >> 5, lane = threadIdx.x & 31;
    int t = blockIdx.x * 8 + warp;
    if (t >= T_TOK) return;
    const float* xr = x + (size_t)t * DIM;
    float xv[24];
#pragma unroll
    for (int j = 0; j < 24; j++) xv[j] = xr[lane + 32 * j];
    float logit[NE];
#pragma unroll
    for (int e = 0; e < NE; e++) {
        float p = 0.f;
#pragma unroll
        for (int j = 0; j < 24; j++) p += xv[j] * sgw[e * DIM + lane + 32 * j];
#pragma unroll
        for (int off = 16; off > 0; off >>= 1) p += __shfl_down_sync(0xffffffffu, p, off);
        logit[e] = p;
    }
    if (lane == 0) {
        float m = logit[0];
#pragma unroll
        for (int e = 1; e < NE; e++) m = fmaxf(m, logit[e]);
        int a = 0;
#pragma unroll
        for (int e = 1; e < NE; e++) if (logit[e] > logit[a]) a = e;
        int b = (a == 0) ? 1 : 0;
#pragma unroll
        for (int e = 0; e < NE; e++) { if (e == a || e == b) continue; if (logit[e] > logit[b]) b = e; }
        float pa = expf(logit[a] - m), pb = expf(logit[b] - m);
        float inv = 1.f / (pa + pb);
        g_slote[2 * t] = a;  g_slote[2 * t + 1] = b;
        g_slotw[2 * t] = pa * inv;  g_slotw[2 * t + 1] = pb * inv;
        atomicAdd(&g_counts[a], 1);
        atomicAdd(&g_counts[b], 1);
    }
}

__global__ void scan_kernel() {
    if (threadIdx.x == 0 && blockIdx.x == 0) {
        int b = 0; g_base[0] = 0;
        for (int e = 0; e < NE; e++) {
            b += ((g_counts[e] + BM - 1) / BM) * BM;
            g_base[e + 1] = b;
        }
    }
}

__global__ void assign_kernel() {
    int t = blockIdx.x * blockDim.x + threadIdx.x;
    if (t >= T_TOK) return;
#pragma unroll
    for (int k = 0; k < 2; k++) {
        int e = g_slote[2 * t + k];
        int pos = atomicAdd(&g_cursor[e], 1);
        int row = g_base[e] + pos;
        g_rowmap[2 * t + k] = row;
        g_rowtoken[row] = t;
    }
}

// fp32 -> fp16 hi/lo split (weights)
__global__ void split_w_kernel(const float* __restrict__ s,
                               __half* __restrict__ hi,
                               __half* __restrict__ lo, int n4) {
    int i = blockIdx.x * blockDim.x + threadIdx.x;
    if (i >= n4) return;
    float4 v = ((const float4*)s)[i];
    float vv[4] = {v.x, v.y, v.z, v.w};
    __half h[4], l[4];
#pragma unroll
    for (int j = 0; j < 4; j++) {
        h[j] = __float2half_rn(vv[j]);
        l[j] = __float2half_rn(vv[j] - __half2float(h[j]));
    }
    ((uint2*)hi)[i] = *(uint2*)h;
    ((uint2*)lo)[i] = *(uint2*)l;
}

// fp32 -> fp16 (activations)
__global__ void split_x_kernel(const float* __restrict__ s,
                               __half* __restrict__ o, int n4) {
    int i = blockIdx.x * blockDim.x + threadIdx.x;
    if (i >= n4) return;
    float4 v = ((const float4*)s)[i];
    __half h[4];
    h[0] = __float2half_rn(v.x); h[1] = __float2half_rn(v.y);
    h[2] = __float2half_rn(v.z); h[3] = __float2half_rn(v.w);
    ((uint2*)o)[i] = *(uint2*)h;
}

// gated eltwise: g_Gp = fp16(gelu(g_G) * g_G3)
__global__ void gated_eltwise_kernel() {
    int i = blockIdx.x * blockDim.x + threadIdx.x;
    int n4 = (int)((size_t)T_TOK * FF / 4);
    if (i >= n4) return;
    float4 a = ((const float4*)g_G)[i];
    float4 b = ((const float4*)g_G3)[i];
    __half h[4];
    h[0] = __float2half_rn(gelu_exact(a.x) * b.x);
    h[1] = __float2half_rn(gelu_exact(a.y) * b.y);
    h[2] = __float2half_rn(gelu_exact(a.z) * b.z);
    h[3] = __float2half_rn(gelu_exact(a.w) * b.w);
    ((uint2*)g_Gp)[i] = *(uint2*)h;
}

__global__ void combine_kernel(float* __restrict__ out) {
    size_t i = (size_t)blockIdx.x * blockDim.x + threadIdx.x;
    if (i >= (size_t)T_TOK * DIM) return;
    int t = (int)(i / DIM), c = (int)(i % DIM);
    float v = out[i];
    int r0 = g_rowmap[2 * t], r1 = g_rowmap[2 * t + 1];
    v += g_slotw[2 * t]     * g_Y[(size_t)r0 * DIM + c];
    v += g_slotw[2 * t + 1] * g_Y[(size_t)r1 * DIM + c];
    out[i] = v;
}

// ---------------- mma.sync fp16 weight-split GEMM ----------------
// C[M,N] = A[M,K] x (Bhi+Blo)[N,K]^T + bias   (A single fp16, B split)
// MODE 0: gelu(acc+bias) -> fp16 Ch
// MODE 1: acc+bias -> fp32 Cf
template<int MODE>
__global__ __launch_bounds__(256, 2) void mma_gemm_kernel(
    const __half* __restrict__ A,
    const __half* __restrict__ Bh, const __half* __restrict__ Bl,
    const float* __restrict__ bias,
    float* __restrict__ Cf, __half* __restrict__ Ch,
    int K, int N, int expert_mode, int gather)
{
    extern __shared__ char smem[];
    uint32_t sb = smem_u32(smem);
    int tid = threadIdx.x;

    int rstart = blockIdx.x * GBM;
    int n0 = blockIdx.y * GBN;

    if (expert_mode) {
        if (rstart >= g_base[NE]) return;
        int e = 0;
#pragma unroll
        for (int i = 0; i < NE; i++) if (rstart >= g_base[i + 1]) e = i + 1;
        size_t wo = (size_t)e * N * K;
        Bh += wo; Bl += wo;
        bias += (size_t)e * N;
    }

    // ---- load assignment: thread t loads row t/2, 32B half (t&1) ----
    int lrow = tid >> 1;
    int lcb  = (tid & 1) * 32;
    int arow_g;
    if (gather) {
        int tok = g_rowtoken[rstart + lrow];
        arow_g = (tok < 0) ? 0 : tok;
    } else {
        arow_g = rstart + lrow;
    }
    const char* pA  = (const char*)(A  + (size_t)arow_g * K) + lcb;
    const char* pBh = (const char*)(Bh + (size_t)(n0 + lrow) * K) + lcb;
    const char* pBl = (const char*)(Bl + (size_t)(n0 + lrow) * K) + lcb;
    uint32_t sA = sb + (uint32_t)(lrow * ROWB + lcb);

    if (tid < 128) ((float*)(smem + SM_BIAS))[tid] = bias[n0 + tid];

    int nk = K / GBK;

#define ISSUE(kc, s) do { \
    uint32_t o = (uint32_t)(s) * STAGEB; \
    size_t g = (size_t)(kc) * 64; \
    CP16(sA + o,            pA  + g); CP16(sA + o + 16,            pA  + g + 16); \
    CP16(sA + o + MATB,     pBh + g); CP16(sA + o + MATB + 16,     pBh + g + 16); \
    CP16(sA + o + 2*MATB,   pBl + g); CP16(sA + o + 2*MATB + 16,   pBl + g + 16); \
    CP_COMMIT(); } while (0)

    ISSUE(0, 0);
    ISSUE(1, 1);
    ISSUE(2, 2);

    int wid = tid >> 5, lane = tid & 31;
    int wm = (wid & 3) * 32;        // warp M offset (32 rows)
    int wn = (wid >> 2) * 64;       // warp N offset (64 cols)
    int lq = lane >> 2;             // 0..7
    int lr = lane & 3;              // 0..3

    // ldmatrix per-lane address offsets (within a stage)
    uint32_t aoff[2], boff[4];
#pragma unroll
    for (int m = 0; m < 2; m++)
        aoff[m] = (uint32_t)((wm + m * 16 + (lane & 15)) * ROWB + ((lane >> 4) << 4));
#pragma unroll
    for (int p = 0; p < 4; p++)
        boff[p] = (uint32_t)((wn + p * 16 + (lane & 7) + ((lane & 16) ? 8 : 0)) * ROWB
                             + ((lane & 8) ? 16 : 0));

    float acc[2][8][4];
#pragma unroll
    for (int m = 0; m < 2; m++)
#pragma unroll
        for (int n = 0; n < 8; n++)
#pragma unroll
            for (int j = 0; j < 4; j++) acc[m][n][j] = 0.f;

    for (int kc = 0; kc < nk; kc++) {
        CP_WAIT2();
        __syncthreads();
        uint32_t st = sb + (uint32_t)(kc % STAGES) * STAGEB;
#pragma unroll
        for (int ks = 0; ks < 2; ks++) {
            uint32_t ko = (uint32_t)(ks * 32);
            uint32_t a[2][4];
            LDSM4(a[0], st + aoff[0] + ko);
            LDSM4(a[1], st + aoff[1] + ko);
#pragma unroll
            for (int p = 0; p < 4; p++) {
                uint32_t bh[4], bl[4];
                LDSM4(bh, st + MATB + boff[p] + ko);
                LDSM4(bl, st + 2 * MATB + boff[p] + ko);
#pragma unroll
                for (int m = 0; m < 2; m++) {
                    mma_f16(acc[m][2 * p],     a[m], bh);
                    mma_f16(acc[m][2 * p],     a[m], bl);
                    mma_f16(acc[m][2 * p + 1], a[m], bh + 2);
                    mma_f16(acc[m][2 * p + 1], a[m], bl + 2);
                }
            }
        }
        __syncthreads();
        if (kc + STAGES < nk) { ISSUE(kc + STAGES, kc % STAGES); }
        else { CP_COMMIT(); }
    }
#undef ISSUE

    // ---- epilogue: registers -> global ----
    const float* sbias = (const float*)(smem + SM_BIAS);
#pragma unroll
    for (int m = 0; m < 2; m++) {
        int r0 = rstart + wm + m * 16 + lq;
#pragma unroll
        for (int n = 0; n < 8; n++) {
            int col = wn + n * 8 + lr * 2;
            float b0 = sbias[col], b1 = sbias[col + 1];
            int gc = n0 + col;
            float v00 = acc[m][n][0] + b0, v01 = acc[m][n][1] + b1;
            float v10 = acc[m][n][2] + b0, v11 = acc[m][n][3] + b1;
            if (MODE == 1) {
                *(float2*)&Cf[(size_t)r0 * N + gc]       = make_float2(v00, v01);
                *(float2*)&Cf[(size_t)(r0 + 8) * N + gc] = make_float2(v10, v11);
            } else {
                __half2 h0, h1;
                h0.x = __float2half_rn(gelu_exact(v00));
                h0.y = __float2half_rn(gelu_exact(v01));
                h1.x = __float2half_rn(gelu_exact(v10));
                h1.y = __float2half_rn(gelu_exact(v11));
                *(__half2*)&Ch[(size_t)r0 * N + gc]       = h0;
                *(__half2*)&Ch[(size_t)(r0 + 8) * N + gc] = h1;
            }
        }
    }
}

// ---------------- launch ----------------
extern "C" void kernel_launch(void* const* d_in, const int* in_sizes, int n_in,
                              void* d_out, int out_size) {
    const float* x      = (const float*)d_in[0];
    const float* gate_w = (const float*)d_in[1];
    const float* fc1_w  = (const float*)d_in[2];
    const float* fc1_b  = (const float*)d_in[3];
    const float* fc2_w  = (const float*)d_in[4];
    const float* fc2_b  = (const float*)d_in[5];
    const float* w1_w   = (const float*)d_in[6];
    const float* w1_b   = (const float*)d_in[7];
    const float* w3_w   = (const float*)d_in[8];
    const float* w3_b   = (const float*)d_in[9];
    const float* w2_w   = (const float*)d_in[10];
    const float* w2_b   = (const float*)d_in[11];
    float* out = (float*)d_out;

    cudaFuncSetAttribute(mma_gemm_kernel<0>, cudaFuncAttributeMaxDynamicSharedMemorySize, SM_TOTAL);
    cudaFuncSetAttribute(mma_gemm_kernel<1>, cudaFuncAttributeMaxDynamicSharedMemorySize, SM_TOTAL);

    // routing metadata
    init_kernel<<<(ROWS_PAD_MAX + 255) / 256, 256>>>();
    gate_kernel<<<T_TOK / 8, 256>>>(x, gate_w);
    scan_kernel<<<1, 32>>>();
    assign_kernel<<<(T_TOK + 255) / 256, 256>>>();

    __half* xh;  cudaGetSymbolAddress((void**)&xh,  g_xh);
    __half* f1h; cudaGetSymbolAddress((void**)&f1h, g_f1h);
    __half* f1l; cudaGetSymbolAddress((void**)&f1l, g_f1l);
    __half* f2h; cudaGetSymbolAddress((void**)&f2h, g_f2h);
    __half* f2l; cudaGetSymbolAddress((void**)&f2l, g_f2l);
    __half* w1h; cudaGetSymbolAddress((void**)&w1h, g_w1h);
    __half* w1l; cudaGetSymbolAddress((void**)&w1l, g_w1l);
    __half* w3h; cudaGetSymbolAddress((void**)&w3h, g_w3h);
    __half* w3l; cudaGetSymbolAddress((void**)&w3l, g_w3l);
    __half* w2h; cudaGetSymbolAddress((void**)&w2h, g_w2h);
    __half* w2l; cudaGetSymbolAddress((void**)&w2l, g_w2l);
    __half* Hh;  cudaGetSymbolAddress((void**)&Hh,  g_H);
    __half* Gp;  cudaGetSymbolAddress((void**)&Gp,  g_Gp);
    float* Gf;  cudaGetSymbolAddress((void**)&Gf,  g_G);
    float* G3f; cudaGetSymbolAddress((void**)&G3f, g_G3);
    float* Yf;  cudaGetSymbolAddress((void**)&Yf,  g_Y);

    auto splitw = [&](const float* s, __half* hi, __half* lo, size_t n) {
        int n4 = (int)(n / 4);
        split_w_kernel<<<(n4 + 255) / 256, 256>>>(s, hi, lo, n4);
    };
    {
        int n4 = (int)((size_t)T_TOK * DIM / 4);
        split_x_kernel<<<(n4 + 255) / 256, 256>>>(x, xh, n4);
    }
    splitw(fc1_w, f1h, f1l, (size_t)NE * FF * DIM);
    splitw(fc2_w, f2h, f2l, (size_t)NE * DIM * FF);
    splitw(w1_w,  w1h, w1l, (size_t)FF * DIM);
    splitw(w3_w,  w3h, w3l, (size_t)FF * DIM);
    splitw(w2_w,  w2h, w2l, (size_t)DIM * FF);

    // routed experts
    mma_gemm_kernel<0><<<dim3(ROW_TILES, FF / GBN), 256, SM_TOTAL>>>(
        xh, f1h, f1l, fc1_b, nullptr, Hh, DIM, FF, 1, 1);
    mma_gemm_kernel<1><<<dim3(ROW_TILES, DIM / GBN), 256, SM_TOTAL>>>(
        Hh, f2h, f2l, fc2_b, Yf, nullptr, FF, DIM, 1, 0);

    // shared gated MLP
    mma_gemm_kernel<1><<<dim3(T_TOK / GBM, FF / GBN), 256, SM_TOTAL>>>(
        xh, w1h, w1l, w1_b, Gf, nullptr, DIM, FF, 0, 0);
    mma_gemm_kernel<1><<<dim3(T_TOK / GBM, FF / GBN), 256, SM_TOTAL>>>(
        xh, w3h, w3l, w3_b, G3f, nullptr, DIM, FF, 0, 0);
    gated_eltwise_kernel<<<(int)(((size_t)T_TOK * FF / 4 + 255) / 256), 256>>>();
    mma_gemm_kernel<1><<<dim3(T_TOK / GBM, DIM / GBN), 256, SM_TOTAL>>>(
        Gp, w2h, w2l, w2_b, out, nullptr, FF, DIM, 0, 0);

    // combine
    combine_kernel<<<(int)(((size_t)T_TOK * DIM + 255) / 256), 256>>>(out);
}

// round 8
// speedup vs baseline: 5.5312x; 1.5973x over previous
#include <cuda_runtime.h>
#include <cuda_fp16.h>
#include <math.h>
#include <stdint.h>

// ---------------- problem constants ----------------
#define T_TOK   16384
#define DIM     768
#define FF      2048
#define NE      8
#define SLOTS   (2*T_TOK)
#define BM      128
#define ROWS_PAD_MAX (SLOTS + NE*BM)   // 33792
#define ROW_TILES    (ROWS_PAD_MAX/BM) // 264

// GEMM tiling
#define GBM 128
#define GBN 128
#define GBK 32                  // K elements per stage chunk (64 bytes/row fp16)
#define ROWB 80                 // padded row stride bytes (64 data + 16 pad)
#define MATB (128*ROWB)         // 10240 bytes per 128-row matrix per stage
#define HMATB (64*ROWB)         // 5120 bytes per 64-row matrix per stage
#define STAGEB (2*MATB)         // 20480: A + B   (gated: A + B1 + B3 = same size)
#define STAGES 3
#define SM_BIAS (STAGES*STAGEB) // 61440
#define SM_TOTAL (SM_BIAS + 512)

// ---------------- device scratch ----------------
__device__ __half g_xh [(size_t)T_TOK * DIM];
__device__ __half g_f1h[(size_t)NE * FF * DIM];
__device__ __half g_f2h[(size_t)NE * DIM * FF];
__device__ __half g_w1h[(size_t)FF * DIM];
__device__ __half g_w3h[(size_t)FF * DIM];
__device__ __half g_w2h[(size_t)DIM * FF];
__device__ __half g_H  [(size_t)ROWS_PAD_MAX * FF];
__device__ __half g_Gp [(size_t)T_TOK * FF];
__device__ float g_Y [(size_t)ROWS_PAD_MAX * DIM];
__device__ int   g_rowtoken[ROWS_PAD_MAX];
__device__ int   g_rowmap[SLOTS];
__device__ float g_slotw[SLOTS];
__device__ int   g_slote[SLOTS];
__device__ int   g_counts[NE];
__device__ int   g_cursor[NE];
__device__ int   g_base[NE+1];

__device__ __forceinline__ float gelu_exact(float v) {
    return 0.5f * v * (1.0f + erff(v * 0.7071067811865475f));
}

// ---------------- PTX helpers (sm_80+ portable) ----------------
__device__ __forceinline__ uint32_t smem_u32(const void* p) {
    uint32_t a;
    asm("{ .reg .u64 t; cvta.to.shared.u64 t, %1; cvt.u32.u64 %0, t; }" : "=r"(a) : "l"(p));
    return a;
}
#define CP16(sa, gp) asm volatile("cp.async.cg.shared.global [%0], [%1], 16;" :: "r"(sa), "l"(gp))
#define CP_COMMIT()  asm volatile("cp.async.commit_group;" ::: "memory")
#define CP_WAIT2()   asm volatile("cp.async.wait_group 2;" ::: "memory")

#define LDSM4(r, a) \
    asm volatile("ldmatrix.sync.aligned.m8n8.x4.shared.b16 {%0,%1,%2,%3}, [%4];" \
        : "=r"((r)[0]), "=r"((r)[1]), "=r"((r)[2]), "=r"((r)[3]) : "r"(a))

__device__ __forceinline__ void mma_f16(float* c, const uint32_t* a, const uint32_t* b) {
    asm volatile(
        "mma.sync.aligned.m16n8k16.row.col.f32.f16.f16.f32 "
        "{%0,%1,%2,%3}, {%4,%5,%6,%7}, {%8,%9}, {%0,%1,%2,%3};"
        : "+f"(c[0]), "+f"(c[1]), "+f"(c[2]), "+f"(c[3])
        : "r"(a[0]), "r"(a[1]), "r"(a[2]), "r"(a[3]), "r"(b[0]), "r"(b[1]));
}

// ---------------- small kernels ----------------
__global__ void init_kernel() {
    int i = blockIdx.x * blockDim.x + threadIdx.x;
    if (i < ROWS_PAD_MAX) g_rowtoken[i] = -1;
    if (i < NE) { g_counts[i] = 0; g_cursor[i] = 0; }
}

__global__ __launch_bounds__(256) void gate_kernel(const float* __restrict__ x,
                                                   const float* __restrict__ gw) {
    __shared__ float sgw[NE * DIM];
    for (int i = threadIdx.x; i < NE * DIM; i += 256) sgw[i] = gw[i];
    __syncthreads();
    int warp = threadIdx.x >> 5, lane = threadIdx.x & 31;
    int t = blockIdx.x * 8 + warp;
    if (t >= T_TOK) return;
    const float* xr = x + (size_t)t * DIM;
    float xv[24];
#pragma unroll
    for (int j = 0; j < 24; j++) xv[j] = xr[lane + 32 * j];
    float logit[NE];
#pragma unroll
    for (int e = 0; e < NE; e++) {
        float p = 0.f;
#pragma unroll
        for (int j = 0; j < 24; j++) p += xv[j] * sgw[e * DIM + lane + 32 * j];
#pragma unroll
        for (int off = 16; off > 0; off >>= 1) p += __shfl_down_sync(0xffffffffu, p, off);
        logit[e] = p;
    }
    if (lane == 0) {
        float m = logit[0];
#pragma unroll
        for (int e = 1; e < NE; e++) m = fmaxf(m, logit[e]);
        int a = 0;
#pragma unroll
        for (int e = 1; e < NE; e++) if (logit[e] > logit[a]) a = e;
        int b = (a == 0) ? 1 : 0;
#pragma unroll
        for (int e = 0; e < NE; e++) { if (e == a || e == b) continue; if (logit[e] > logit[b]) b = e; }
        float pa = expf(logit[a] - m), pb = expf(logit[b] - m);
        float inv = 1.f / (pa + pb);
        g_slote[2 * t] = a;  g_slote[2 * t + 1] = b;
        g_slotw[2 * t] = pa * inv;  g_slotw[2 * t + 1] = pb * inv;
        atomicAdd(&g_counts[a], 1);
        atomicAdd(&g_counts[b], 1);
    }
}

__global__ void scan_kernel() {
    if (threadIdx.x == 0 && blockIdx.x == 0) {
        int b = 0; g_base[0] = 0;
        for (int e = 0; e < NE; e++) {
            b += ((g_counts[e] + BM - 1) / BM) * BM;
            g_base[e + 1] = b;
        }
    }
}

__global__ void assign_kernel() {
    int t = blockIdx.x * blockDim.x + threadIdx.x;
    if (t >= T_TOK) return;
#pragma unroll
    for (int k = 0; k < 2; k++) {
        int e = g_slote[2 * t + k];
        int pos = atomicAdd(&g_cursor[e], 1);
        int row = g_base[e] + pos;
        g_rowmap[2 * t + k] = row;
        g_rowtoken[row] = t;
    }
}

// fp32 -> fp16 conversion
__global__ void conv_kernel(const float* __restrict__ s,
                            __half* __restrict__ o, int n4) {
    int i = blockIdx.x * blockDim.x + threadIdx.x;
    if (i >= n4) return;
    float4 v = ((const float4*)s)[i];
    __half h[4];
    h[0] = __float2half_rn(v.x); h[1] = __float2half_rn(v.y);
    h[2] = __float2half_rn(v.z); h[3] = __float2half_rn(v.w);
    ((uint2*)o)[i] = *(uint2*)h;
}

__global__ void combine_kernel(float* __restrict__ out) {
    size_t i = (size_t)blockIdx.x * blockDim.x + threadIdx.x;
    if (i >= (size_t)T_TOK * DIM) return;
    int t = (int)(i / DIM), c = (int)(i % DIM);
    float v = out[i];
    int r0 = g_rowmap[2 * t], r1 = g_rowmap[2 * t + 1];
    v += g_slotw[2 * t]     * g_Y[(size_t)r0 * DIM + c];
    v += g_slotw[2 * t + 1] * g_Y[(size_t)r1 * DIM + c];
    out[i] = v;
}

// ---------------- mma.sync fp16 GEMM ----------------
// C[M,N] = A[M,K] x B[N,K]^T + bias
// MODE 0: gelu(acc+bias) -> fp16 Ch ;  MODE 1: acc+bias -> fp32 Cf
template<int MODE>
__global__ __launch_bounds__(256, 2) void mma_gemm_kernel(
    const __half* __restrict__ A, const __half* __restrict__ B,
    const float* __restrict__ bias,
    float* __restrict__ Cf, __half* __restrict__ Ch,
    int K, int N, int expert_mode, int gather)
{
    extern __shared__ char smem[];
    uint32_t sb = smem_u32(smem);
    int tid = threadIdx.x;

    int rstart = blockIdx.x * GBM;
    int n0 = blockIdx.y * GBN;

    if (expert_mode) {
        if (rstart >= g_base[NE]) return;
        int e = 0;
#pragma unroll
        for (int i = 0; i < NE; i++) if (rstart >= g_base[i + 1]) e = i + 1;
        B += (size_t)e * N * K;
        bias += (size_t)e * N;
    }

    // loads: thread t loads row t/2, 32B half (t&1)
    int lrow = tid >> 1;
    int lcb  = (tid & 1) * 32;
    int arow_g;
    if (gather) {
        int tok = g_rowtoken[rstart + lrow];
        arow_g = (tok < 0) ? 0 : tok;
    } else {
        arow_g = rstart + lrow;
    }
    const char* pA = (const char*)(A + (size_t)arow_g * K) + lcb;
    const char* pB = (const char*)(B + (size_t)(n0 + lrow) * K) + lcb;
    uint32_t sA = sb + (uint32_t)(lrow * ROWB + lcb);

    if (tid < 128) ((float*)(smem + SM_BIAS))[tid] = bias[n0 + tid];

    int nk = K / GBK;

#define ISSUE(kc, s) do { \
    uint32_t o = (uint32_t)(s) * STAGEB; \
    size_t g = (size_t)(kc) * 64; \
    CP16(sA + o,          pA + g); CP16(sA + o + 16,        pA + g + 16); \
    CP16(sA + o + MATB,   pB + g); CP16(sA + o + MATB + 16, pB + g + 16); \
    CP_COMMIT(); } while (0)

    ISSUE(0, 0);
    ISSUE(1, 1);
    ISSUE(2, 2);

    int wid = tid >> 5, lane = tid & 31;
    int wm = (wid & 3) * 32;
    int wn = (wid >> 2) * 64;
    int lq = lane >> 2;
    int lr = lane & 3;

    uint32_t aoff[2], boff[4];
#pragma unroll
    for (int m = 0; m < 2; m++)
        aoff[m] = (uint32_t)((wm + m * 16 + (lane & 15)) * ROWB + ((lane >> 4) << 4));
#pragma unroll
    for (int p = 0; p < 4; p++)
        boff[p] = (uint32_t)((wn + p * 16 + (lane & 7) + ((lane & 16) ? 8 : 0)) * ROWB
                             + ((lane & 8) ? 16 : 0));

    float acc[2][8][4];
#pragma unroll
    for (int m = 0; m < 2; m++)
#pragma unroll
        for (int n = 0; n < 8; n++)
#pragma unroll
            for (int j = 0; j < 4; j++) acc[m][n][j] = 0.f;

    for (int kc = 0; kc < nk; kc++) {
        CP_WAIT2();
        __syncthreads();
        uint32_t st = sb + (uint32_t)(kc % STAGES) * STAGEB;
#pragma unroll
        for (int ks = 0; ks < 2; ks++) {
            uint32_t ko = (uint32_t)(ks * 32);
            uint32_t a[2][4];
            LDSM4(a[0], st + aoff[0] + ko);
            LDSM4(a[1], st + aoff[1] + ko);
#pragma unroll
            for (int p = 0; p < 4; p++) {
                uint32_t bh[4];
                LDSM4(bh, st + MATB + boff[p] + ko);
#pragma unroll
                for (int m = 0; m < 2; m++) {
                    mma_f16(acc[m][2 * p],     a[m], bh);
                    mma_f16(acc[m][2 * p + 1], a[m], bh + 2);
                }
            }
        }
        __syncthreads();
        if (kc + STAGES < nk) { ISSUE(kc + STAGES, kc % STAGES); }
        else { CP_COMMIT(); }
    }
#undef ISSUE

    const float* sbias = (const float*)(smem + SM_BIAS);
#pragma unroll
    for (int m = 0; m < 2; m++) {
        int r0 = rstart + wm + m * 16 + lq;
#pragma unroll
        for (int n = 0; n < 8; n++) {
            int col = wn + n * 8 + lr * 2;
            float b0 = sbias[col], b1 = sbias[col + 1];
            int gc = n0 + col;
            float v00 = acc[m][n][0] + b0, v01 = acc[m][n][1] + b1;
            float v10 = acc[m][n][2] + b0, v11 = acc[m][n][3] + b1;
            if (MODE == 1) {
                *(float2*)&Cf[(size_t)r0 * N + gc]       = make_float2(v00, v01);
                *(float2*)&Cf[(size_t)(r0 + 8) * N + gc] = make_float2(v10, v11);
            } else {
                __half2 h0, h1;
                h0.x = __float2half_rn(gelu_exact(v00));
                h0.y = __float2half_rn(gelu_exact(v01));
                h1.x = __float2half_rn(gelu_exact(v10));
                h1.y = __float2half_rn(gelu_exact(v11));
                *(__half2*)&Ch[(size_t)r0 * N + gc]       = h0;
                *(__half2*)&Ch[(size_t)(r0 + 8) * N + gc] = h1;
            }
        }
    }
}

// ---------------- fused w1/w3 gated MLP front ----------------
// For a 128x64 tile: h1 = x*w1^T+b1, h3 = x*w3^T+b3, Gp = fp16(gelu(h1)*h3)
__global__ __launch_bounds__(256, 2) void gated_mma_kernel(
    const __half* __restrict__ A,
    const __half* __restrict__ B1, const __half* __restrict__ B3,
    const float* __restrict__ bias1, const float* __restrict__ bias3,
    __half* __restrict__ Gp)
{
    extern __shared__ char smem[];
    uint32_t sb = smem_u32(smem);
    int tid = threadIdx.x;
    int rstart = blockIdx.x * GBM;
    int n0 = blockIdx.y * 64;

    // A loads: thread t -> row t/2, 32B half
    int lrow = tid >> 1;
    int lcb  = (tid & 1) * 32;
    const char* pA = (const char*)(A + (size_t)(rstart + lrow) * DIM) + lcb;
    uint32_t sA = sb + (uint32_t)(lrow * ROWB + lcb);
    // B loads: thread t -> row t/4 (0..63), 16B quarter
    int brow = tid >> 2;
    int bq   = (tid & 3) * 16;
    const char* pB1 = (const char*)(B1 + (size_t)(n0 + brow) * DIM) + bq;
    const char* pB3 = (const char*)(B3 + (size_t)(n0 + brow) * DIM) + bq;
    uint32_t sB = sb + (uint32_t)(brow * ROWB + bq);

    if (tid < 64) {
        ((float*)(smem + SM_BIAS))[tid]      = bias1[n0 + tid];
        ((float*)(smem + SM_BIAS))[64 + tid] = bias3[n0 + tid];
    }

    const int nk = DIM / GBK;

#define ISSUE_G(kc, s) do { \
    uint32_t o = (uint32_t)(s) * STAGEB; \
    size_t g = (size_t)(kc) * 64; \
    CP16(sA + o,                    pA  + g); CP16(sA + o + 16, pA + g + 16); \
    CP16(sB + o + MATB,             pB1 + g); \
    CP16(sB + o + MATB + HMATB,     pB3 + g); \
    CP_COMMIT(); } while (0)

    ISSUE_G(0, 0);
    ISSUE_G(1, 1);
    ISSUE_G(2, 2);

    int wid = tid >> 5, lane = tid & 31;
    int wm = (wid & 3) * 32;
    int wn = (wid >> 2) * 32;
    int lq = lane >> 2;
    int lr = lane & 3;

    uint32_t aoff[2], boff[2];
#pragma unroll
    for (int m = 0; m < 2; m++)
        aoff[m] = (uint32_t)((wm + m * 16 + (lane & 15)) * ROWB + ((lane >> 4) << 4));
#pragma unroll
    for (int p = 0; p < 2; p++)
        boff[p] = (uint32_t)((wn + p * 16 + (lane & 7) + ((lane & 16) ? 8 : 0)) * ROWB
                             + ((lane & 8) ? 16 : 0));

    float acc1[2][4][4], acc3[2][4][4];
#pragma unroll
    for (int m = 0; m < 2; m++)
#pragma unroll
        for (int n = 0; n < 4; n++)
#pragma unroll
            for (int j = 0; j < 4; j++) { acc1[m][n][j] = 0.f; acc3[m][n][j] = 0.f; }

    for (int kc = 0; kc < nk; kc++) {
        CP_WAIT2();
        __syncthreads();
        uint32_t st = sb + (uint32_t)(kc % STAGES) * STAGEB;
#pragma unroll
        for (int ks = 0; ks < 2; ks++) {
            uint32_t ko = (uint32_t)(ks * 32);
            uint32_t a[2][4];
            LDSM4(a[0], st + aoff[0] + ko);
            LDSM4(a[1], st + aoff[1] + ko);
#pragma unroll
            for (int p = 0; p < 2; p++) {
                uint32_t b1[4], b3[4];
                LDSM4(b1, st + MATB + boff[p] + ko);
                LDSM4(b3, st + MATB + HMATB + boff[p] + ko);
#pragma unroll
                for (int m = 0; m < 2; m++) {
                    mma_f16(acc1[m][2 * p],     a[m], b1);
                    mma_f16(acc1[m][2 * p + 1], a[m], b1 + 2);
                    mma_f16(acc3[m][2 * p],     a[m], b3);
                    mma_f16(acc3[m][2 * p + 1], a[m], b3 + 2);
                }
            }
        }
        __syncthreads();
        if (kc + STAGES < nk) { ISSUE_G(kc + STAGES, kc % STAGES); }
        else { CP_COMMIT(); }
    }
#undef ISSUE_G

    const float* b1s = (const float*)(smem + SM_BIAS);
    const float* b3s = b1s + 64;
#pragma unroll
    for (int m = 0; m < 2; m++) {
        int r0 = rstart + wm + m * 16 + lq;
#pragma unroll
        for (int n = 0; n < 4; n++) {
            int col = wn + n * 8 + lr * 2;
            float c10 = b1s[col], c11 = b1s[col + 1];
            float c30 = b3s[col], c31 = b3s[col + 1];
            int gc = n0 + col;
            __half2 h0, h1;
            h0.x = __float2half_rn(gelu_exact(acc1[m][n][0] + c10) * (acc3[m][n][0] + c30));
            h0.y = __float2half_rn(gelu_exact(acc1[m][n][1] + c11) * (acc3[m][n][1] + c31));
            h1.x = __float2half_rn(gelu_exact(acc1[m][n][2] + c10) * (acc3[m][n][2] + c30));
            h1.y = __float2half_rn(gelu_exact(acc1[m][n][3] + c11) * (acc3[m][n][3] + c31));
            *(__half2*)&Gp[(size_t)r0 * FF + gc]       = h0;
            *(__half2*)&Gp[(size_t)(r0 + 8) * FF + gc] = h1;
        }
    }
}

// ---------------- launch ----------------
extern "C" void kernel_launch(void* const* d_in, const int* in_sizes, int n_in,
                              void* d_out, int out_size) {
    const float* x      = (const float*)d_in[0];
    const float* gate_w = (const float*)d_in[1];
    const float* fc1_w  = (const float*)d_in[2];
    const float* fc1_b  = (const float*)d_in[3];
    const float* fc2_w  = (const float*)d_in[4];
    const float* fc2_b  = (const float*)d_in[5];
    const float* w1_w   = (const float*)d_in[6];
    const float* w1_b   = (const float*)d_in[7];
    const float* w3_w   = (const float*)d_in[8];
    const float* w3_b   = (const float*)d_in[9];
    const float* w2_w   = (const float*)d_in[10];
    const float* w2_b   = (const float*)d_in[11];
    float* out = (float*)d_out;

    cudaFuncSetAttribute(mma_gemm_kernel<0>, cudaFuncAttributeMaxDynamicSharedMemorySize, SM_TOTAL);
    cudaFuncSetAttribute(mma_gemm_kernel<1>, cudaFuncAttributeMaxDynamicSharedMemorySize, SM_TOTAL);
    cudaFuncSetAttribute(gated_mma_kernel,   cudaFuncAttributeMaxDynamicSharedMemorySize, SM_TOTAL);

    // routing metadata
    init_kernel<<<(ROWS_PAD_MAX + 255) / 256, 256>>>();
    gate_kernel<<<T_TOK / 8, 256>>>(x, gate_w);
    scan_kernel<<<1, 32>>>();
    assign_kernel<<<(T_TOK + 255) / 256, 256>>>();

    __half* xh;  cudaGetSymbolAddress((void**)&xh,  g_xh);
    __half* f1h; cudaGetSymbolAddress((void**)&f1h, g_f1h);
    __half* f2h; cudaGetSymbolAddress((void**)&f2h, g_f2h);
    __half* w1h; cudaGetSymbolAddress((void**)&w1h, g_w1h);
    __half* w3h; cudaGetSymbolAddress((void**)&w3h, g_w3h);
    __half* w2h; cudaGetSymbolAddress((void**)&w2h, g_w2h);
    __half* Hh;  cudaGetSymbolAddress((void**)&Hh,  g_H);
    __half* Gp;  cudaGetSymbolAddress((void**)&Gp,  g_Gp);
    float* Yf;  cudaGetSymbolAddress((void**)&Yf,  g_Y);

    auto conv = [&](const float* s, __half* o, size_t n) {
        int n4 = (int)(n / 4);
        conv_kernel<<<(n4 + 255) / 256, 256>>>(s, o, n4);
    };
    conv(x,     xh,  (size_t)T_TOK * DIM);
    conv(fc1_w, f1h, (size_t)NE * FF * DIM);
    conv(fc2_w, f2h, (size_t)NE * DIM * FF);
    conv(w1_w,  w1h, (size_t)FF * DIM);
    conv(w3_w,  w3h, (size_t)FF * DIM);
    conv(w2_w,  w2h, (size_t)DIM * FF);

    // routed experts
    mma_gemm_kernel<0><<<dim3(ROW_TILES, FF / GBN), 256, SM_TOTAL>>>(
        xh, f1h, fc1_b, nullptr, Hh, DIM, FF, 1, 1);
    mma_gemm_kernel<1><<<dim3(ROW_TILES, DIM / GBN), 256, SM_TOTAL>>>(
        Hh, f2h, fc2_b, Yf, nullptr, FF, DIM, 1, 0);

    // shared gated MLP: fused w1+w3+eltwise, then w2
    gated_mma_kernel<<<dim3(T_TOK / GBM, FF / 64), 256, SM_TOTAL>>>(
        xh, w1h, w3h, w1_b, w3_b, Gp);
    mma_gemm_kernel<1><<<dim3(T_TOK / GBM, DIM / GBN), 256, SM_TOTAL>>>(
        Gp, w2h, w2_b, out, nullptr, FF, DIM, 0, 0);

    // combine
    combine_kernel<<<(int)(((size_t)T_TOK * DIM + 255) / 256), 256>>>(out);
}